// round 11
// baseline (speedup 1.0000x reference)
#include <cuda_runtime.h>
#include <stdint.h>
#include <math.h>

// ---------------- problem constants ----------------
#define CDIM   1024
#define NTOK   16384             // B*T = 4*4096
#define C3     (3 * CDIM)        // 3072

// ---------------- scratch (allocation-free rule) ----------------
__device__ float g_qkv[(size_t)NTOK * C3];
__device__ float g_y  [(size_t)NTOK * CDIM];
__device__ float g_xt [(size_t)NTOK * CDIM];
__device__ float g_w1t[(size_t)C3 * CDIM];
__device__ float g_w2t[(size_t)CDIM * CDIM];

// ---------------- PTX helpers (baseline sm_80+ only) ----------------
__device__ __forceinline__ uint32_t smem_u32(const void* p) {
    uint32_t a;
    asm("{ .reg .u64 t; cvta.to.shared.u64 t, %1; cvt.u32.u64 %0, t; }"
        : "=r"(a) : "l"(p));
    return a;
}

#define CP_ASYNC16(dst_u32, src_ptr) \
    asm volatile("cp.async.cg.shared.global [%0], [%1], 16;" \
                 :: "r"(dst_u32), "l"(src_ptr) : "memory")
#define CP_COMMIT() asm volatile("cp.async.commit_group;" ::: "memory")
#define CP_WAIT(n)  asm volatile("cp.async.wait_group %0;" :: "n"(n) : "memory")

#define LDSM4(r, addr) \
    asm volatile("ldmatrix.sync.aligned.m8n8.x4.shared.b16 {%0,%1,%2,%3}, [%4];" \
        : "=r"((r)[0]), "=r"((r)[1]), "=r"((r)[2]), "=r"((r)[3]) : "r"(addr))

#define MMA_TF32(d, a, b0, b1) \
    asm volatile("mma.sync.aligned.m16n8k8.row.col.f32.tf32.tf32.f32 " \
        "{%0,%1,%2,%3}, {%4,%5,%6,%7}, {%8,%9}, {%0,%1,%2,%3};" \
        : "+f"((d)[0]), "+f"((d)[1]), "+f"((d)[2]), "+f"((d)[3]) \
        : "r"((a)[0]), "r"((a)[1]), "r"((a)[2]), "r"((a)[3]), "r"(b0), "r"(b1))

__device__ __forceinline__ uint32_t f2tf32(float x) {
    uint32_t r;
    asm("cvt.rna.tf32.f32 %0, %1;" : "=r"(r) : "f"(x));
    return r;
}

// ---------------- GEMM smem geometry (XOR swizzle, pitch = 128 B exact) ----------------
#define PITCH   128
#define TILE_B  (128 * PITCH)      // 16384 B
#define OFF_B   TILE_B
#define STAGE_B (2 * TILE_B)       // 32768 B
#define NSTG    3
#define SMEM_B  (NSTG * STAGE_B)   // 98304 B -> 2 CTAs/SM
#define BKC     32                 // K per chunk (4 k8 steps)

// 64x128 variant geometry
#define A64_B   (64 * PITCH)               // 8192
#define OFF64   A64_B
#define STG64_B (A64_B + 128 * PITCH)      // 24576
#define SMEM64  (NSTG * STG64_B)           // 73728

// ---------------------------------------------------------------------------
// GEMM 128x128 — identical to round 8/10 (at the tf32-MMA instruction floor).
// ---------------------------------------------------------------------------
__global__ __launch_bounds__(256, 2) void tf32_gemm(
    const float* __restrict__ A, const float* __restrict__ B,
    const float* __restrict__ bias, float* __restrict__ C,
    int M, int N, int K)
{
    extern __shared__ char sm[];
    const uint32_t sbase = smem_u32(sm);

    const int tid  = threadIdx.x;
    const int lane = tid & 31;
    const int wid  = tid >> 5;
    const int wm   = wid & 1;
    const int wn   = wid >> 1;
    const int bm   = blockIdx.y * 128;
    const int bn   = blockIdx.x * 128;

    const int lr = tid >> 1;
    const int lh = tid & 1;
    const float* gA = A + (size_t)(bm + lr) * K + lh * 16;
    const float* gB = B + (size_t)(bn + lr) * K + lh * 16;
    uint32_t sw[4];
    #pragma unroll
    for (int j = 0; j < 4; j++) sw[j] = (uint32_t)(((lh * 4 + j) ^ (lr & 7)) << 4);
    const uint32_t sRowBase = (uint32_t)(lr * PITCH);

    const int g  = lane >> 3;
    const int l8 = lane & 7;
    const int cA = g >> 1;
    const int cB = g & 1;
    const uint32_t aRow = (uint32_t)((wm * 64 + l8 + (g & 1) * 8) * PITCH);
    const uint32_t bRow = (uint32_t)((wn * 32 + l8 + (g >> 1) * 8) * PITCH);
    uint32_t aSw[4], bSw[4];
    #pragma unroll
    for (int s = 0; s < 4; s++) {
        aSw[s] = (uint32_t)(((s * 2 + cA) ^ l8) << 4);
        bSw[s] = (uint32_t)(((s * 2 + cB) ^ l8) << 4);
    }

    float acc[4][4][4];
    #pragma unroll
    for (int i = 0; i < 4; i++)
        #pragma unroll
        for (int j = 0; j < 4; j++)
            #pragma unroll
            for (int q = 0; q < 4; q++) acc[i][j][q] = 0.0f;

    const int KC = K / BKC;

    auto issue = [&](int stg, int ko) {
        const uint32_t dA = sbase + (uint32_t)stg * STAGE_B + sRowBase;
        const uint32_t dB = dA + OFF_B;
        const float* sa = gA + ko;
        const float* sb = gB + ko;
        #pragma unroll
        for (int j = 0; j < 4; j++) {
            CP_ASYNC16(dA + sw[j], sa + j * 4);
            CP_ASYNC16(dB + sw[j], sb + j * 4);
        }
    };

    issue(0, 0);   CP_COMMIT();
    issue(1, BKC); CP_COMMIT();

    uint32_t af[2][4][4], bf[2][2][4];

    for (int c = 0; c < KC; c++) {
        if (c == KC - 1) { CP_WAIT(0); } else { CP_WAIT(1); }
        __syncthreads();
        if (c + 2 < KC) { issue((c + 2) % NSTG, (c + 2) * BKC); CP_COMMIT(); }

        const uint32_t stg = sbase + (uint32_t)(c % NSTG) * STAGE_B;
        const uint32_t aB  = stg + aRow;
        const uint32_t bB  = stg + OFF_B + bRow;

        #pragma unroll
        for (int i = 0; i < 4; i++) LDSM4(af[0][i], aB + aSw[0] + (uint32_t)(i * 16 * PITCH));
        #pragma unroll
        for (int p = 0; p < 2; p++) LDSM4(bf[0][p], bB + bSw[0] + (uint32_t)(p * 16 * PITCH));

        #pragma unroll
        for (int s = 0; s < 4; s++) {
            const int cur = s & 1;
            const int nxt = cur ^ 1;
            #pragma unroll
            for (int m = 0; m < 16; m++) {
                const int i = m >> 2, j = m & 3;
                const int p = j >> 1, q = j & 1;
                MMA_TF32(acc[i][j], af[cur][i], bf[cur][p][q * 2], bf[cur][p][q * 2 + 1]);
                if (s < 3) {
                    if (m == 2)
                        LDSM4(af[nxt][0], aB + aSw[s + 1] + (uint32_t)(0 * 16 * PITCH));
                    if (m == 4)
                        LDSM4(af[nxt][1], aB + aSw[s + 1] + (uint32_t)(1 * 16 * PITCH));
                    if (m == 6)
                        LDSM4(af[nxt][2], aB + aSw[s + 1] + (uint32_t)(2 * 16 * PITCH));
                    if (m == 8)
                        LDSM4(af[nxt][3], aB + aSw[s + 1] + (uint32_t)(3 * 16 * PITCH));
                    if (m == 10)
                        LDSM4(bf[nxt][0], bB + bSw[s + 1] + (uint32_t)(0 * 16 * PITCH));
                    if (m == 12)
                        LDSM4(bf[nxt][1], bB + bSw[s + 1] + (uint32_t)(1 * 16 * PITCH));
                }
            }
        }
    }

    #pragma unroll
    for (int i = 0; i < 4; i++) {
        const int row = bm + wm * 64 + i * 16 + (lane >> 2);
        #pragma unroll
        for (int j = 0; j < 4; j++) {
            const int col = bn + wn * 32 + j * 8 + (lane & 3) * 2;
            float b0 = 0.f, b1 = 0.f;
            if (bias) { b0 = bias[col]; b1 = bias[col + 1]; }
            float2 v0 = make_float2(acc[i][j][0] + b0, acc[i][j][1] + b1);
            float2 v1 = make_float2(acc[i][j][2] + b0, acc[i][j][3] + b1);
            *(float2*)(C + (size_t)row * N + col)       = v0;
            *(float2*)(C + (size_t)(row + 8) * N + col) = v1;
        }
    }
}

// ---------------------------------------------------------------------------
// GEMM 64x128 — same machinery, half the M-tile, for fine wave granularity.
// Warp tile 32x32 (wm: 2x32 rows, wn: 4x32 cols).
// ---------------------------------------------------------------------------
__global__ __launch_bounds__(256, 2) void tf32_gemm_64(
    const float* __restrict__ A, const float* __restrict__ B,
    const float* __restrict__ bias, float* __restrict__ C,
    int M, int N, int K)
{
    extern __shared__ char sm[];
    const uint32_t sbase = smem_u32(sm);

    const int tid  = threadIdx.x;
    const int lane = tid & 31;
    const int wid  = tid >> 5;
    const int wm   = wid & 1;
    const int wn   = wid >> 1;
    const int bm   = blockIdx.y * 64;
    const int bn   = blockIdx.x * 128;

    // A loader: 64 rows x 8 chunks; thread -> (row tid>>2, chunk pair tid&3)
    const int rowA = tid >> 2;
    const int pA   = tid & 3;
    const float* gA = A + (size_t)(bm + rowA) * K + pA * 8;
    uint32_t swA[2];
    #pragma unroll
    for (int jj = 0; jj < 2; jj++)
        swA[jj] = (uint32_t)(((2 * pA + jj) ^ (rowA & 7)) << 4);
    const uint32_t sRowA = (uint32_t)(rowA * PITCH);

    // B loader: 128 rows x 8 chunks; thread -> (row tid>>1, half tid&1)
    const int rowB = tid >> 1;
    const int hB   = tid & 1;
    const float* gB = B + (size_t)(bn + rowB) * K + hB * 16;
    uint32_t swB[4];
    #pragma unroll
    for (int j = 0; j < 4; j++)
        swB[j] = (uint32_t)(((hB * 4 + j) ^ (rowB & 7)) << 4);
    const uint32_t sRowB = (uint32_t)(rowB * PITCH);

    // ldmatrix lane addressing
    const int g  = lane >> 3;
    const int l8 = lane & 7;
    const int cA = g >> 1;
    const int cB = g & 1;
    const uint32_t aRow = (uint32_t)((wm * 32 + l8 + (g & 1) * 8) * PITCH);
    const uint32_t bRow = (uint32_t)((wn * 32 + l8 + (g >> 1) * 8) * PITCH);
    uint32_t aSw[4], bSw[4];
    #pragma unroll
    for (int s = 0; s < 4; s++) {
        aSw[s] = (uint32_t)(((s * 2 + cA) ^ l8) << 4);
        bSw[s] = (uint32_t)(((s * 2 + cB) ^ l8) << 4);
    }

    float acc[2][4][4];
    #pragma unroll
    for (int i = 0; i < 2; i++)
        #pragma unroll
        for (int j = 0; j < 4; j++)
            #pragma unroll
            for (int q = 0; q < 4; q++) acc[i][j][q] = 0.0f;

    const int KC = K / BKC;

    auto issue = [&](int stg, int ko) {
        const uint32_t dA = sbase + (uint32_t)stg * STG64_B + sRowA;
        const uint32_t dB = sbase + (uint32_t)stg * STG64_B + OFF64 + sRowB;
        const float* sa = gA + ko;
        const float* sb = gB + ko;
        #pragma unroll
        for (int jj = 0; jj < 2; jj++) CP_ASYNC16(dA + swA[jj], sa + jj * 4);
        #pragma unroll
        for (int j = 0; j < 4; j++)  CP_ASYNC16(dB + swB[j], sb + j * 4);
    };

    issue(0, 0);   CP_COMMIT();
    issue(1, BKC); CP_COMMIT();

    uint32_t af[2][2][4], bf[2][2][4];

    for (int c = 0; c < KC; c++) {
        if (c == KC - 1) { CP_WAIT(0); } else { CP_WAIT(1); }
        __syncthreads();
        if (c + 2 < KC) { issue((c + 2) % NSTG, (c + 2) * BKC); CP_COMMIT(); }

        const uint32_t stg = sbase + (uint32_t)(c % NSTG) * STG64_B;
        const uint32_t aB  = stg + aRow;
        const uint32_t bB  = stg + OFF64 + bRow;

        #pragma unroll
        for (int i = 0; i < 2; i++) LDSM4(af[0][i], aB + aSw[0] + (uint32_t)(i * 16 * PITCH));
        #pragma unroll
        for (int p = 0; p < 2; p++) LDSM4(bf[0][p], bB + bSw[0] + (uint32_t)(p * 16 * PITCH));

        #pragma unroll
        for (int s = 0; s < 4; s++) {
            const int cur = s & 1;
            const int nxt = cur ^ 1;
            #pragma unroll
            for (int m = 0; m < 8; m++) {
                const int i = m >> 2, j = m & 3;
                const int p = j >> 1, q = j & 1;
                MMA_TF32(acc[i][j], af[cur][i], bf[cur][p][q * 2], bf[cur][p][q * 2 + 1]);
                if (s < 3) {
                    if (m == 1)
                        LDSM4(af[nxt][0], aB + aSw[s + 1] + (uint32_t)(0 * 16 * PITCH));
                    if (m == 3)
                        LDSM4(af[nxt][1], aB + aSw[s + 1] + (uint32_t)(1 * 16 * PITCH));
                    if (m == 5)
                        LDSM4(bf[nxt][0], bB + bSw[s + 1] + (uint32_t)(0 * 16 * PITCH));
                    if (m == 6)
                        LDSM4(bf[nxt][1], bB + bSw[s + 1] + (uint32_t)(1 * 16 * PITCH));
                }
            }
        }
    }

    #pragma unroll
    for (int i = 0; i < 2; i++) {
        const int row = bm + wm * 32 + i * 16 + (lane >> 2);
        #pragma unroll
        for (int j = 0; j < 4; j++) {
            const int col = bn + wn * 32 + j * 8 + (lane & 3) * 2;
            float b0 = 0.f, b1 = 0.f;
            if (bias) { b0 = bias[col]; b1 = bias[col + 1]; }
            float2 v0 = make_float2(acc[i][j][0] + b0, acc[i][j][1] + b1);
            float2 v1 = make_float2(acc[i][j][2] + b0, acc[i][j][3] + b1);
            *(float2*)(C + (size_t)row * N + col)       = v0;
            *(float2*)(C + (size_t)(row + 8) * N + col) = v1;
        }
    }
}

// ---------------------------------------------------------------------------
// Merged tf32 rounding: one launch for x, Wqkv, Wout (grid-stride).
// ---------------------------------------------------------------------------
#define N4_X  (NTOK * CDIM / 4)
#define N4_W1 (C3 * CDIM / 4)
#define N4_W2 (CDIM * CDIM / 4)

__global__ __launch_bounds__(256) void round_all_kernel(
    const float* __restrict__ x,  float* __restrict__ xt,
    const float* __restrict__ w1, float* __restrict__ w1t,
    const float* __restrict__ w2, float* __restrict__ w2t)
{
    const int total = N4_X + N4_W1 + N4_W2;
    for (int i = blockIdx.x * blockDim.x + threadIdx.x; i < total;
         i += gridDim.x * blockDim.x) {
        const float4* s;
        float* d;
        int k;
        if (i < N4_X)               { s = (const float4*)x;  d = xt;  k = i; }
        else if (i < N4_X + N4_W1)  { s = (const float4*)w1; d = w1t; k = i - N4_X; }
        else                        { s = (const float4*)w2; d = w2t; k = i - N4_X - N4_W1; }
        const float4 v = s[k];
        uint4 r;
        r.x = f2tf32(v.x); r.y = f2tf32(v.y);
        r.z = f2tf32(v.z); r.w = f2tf32(v.w);
        ((uint4*)d)[k] = r;
    }
}

// ---------------------------------------------------------------------------
// Attention over heads — register-tiled (round 10, unchanged).
// ---------------------------------------------------------------------------
#define TOKPC  8
#define RPITCH 68
#define POFF   3264
#define TPITCH 3544
#define ATTN_SMEM (TOKPC * TPITCH * 4)

__global__ __launch_bounds__(128) void attn_kernel(
    const float* __restrict__ qkv, float* __restrict__ y)
{
    extern __shared__ float sh[];
    const int tid = threadIdx.x;
    const int tokBlk = blockIdx.x * TOKPC;

    const float4* src = (const float4*)(qkv + (size_t)tokBlk * C3);
    #pragma unroll
    for (int it = 0; it < (TOKPC * 768) / 128; it++) {
        const int i  = it * 128 + tid;
        const int t  = i / 768;
        const int rr = (i % 768) >> 4;
        const int c4 = i & 15;
        *(float4*)(sh + t * TPITCH + rr * RPITCH + c4 * 4) = src[i];
    }
    __syncthreads();

    const int tok = tid >> 4;
    const int j   = tid & 15;
    const int I   = j >> 2;
    const int J   = j & 3;
    float* tb = sh + tok * TPITCH;

    float s[4][4];
    #pragma unroll
    for (int r = 0; r < 4; r++)
        #pragma unroll
        for (int c = 0; c < 4; c++) s[r][c] = 0.0f;

    #pragma unroll
    for (int dd = 0; dd < 16; dd++) {
        float4 qv[4], kv[4];
        #pragma unroll
        for (int r = 0; r < 4; r++)
            qv[r] = *(const float4*)(tb + (12 * I + 3 * r) * RPITCH + dd * 4);
        #pragma unroll
        for (int c = 0; c < 4; c++)
            kv[c] = *(const float4*)(tb + (12 * J + 3 * c + 1) * RPITCH + dd * 4);
        #pragma unroll
        for (int r = 0; r < 4; r++)
            #pragma unroll
            for (int c = 0; c < 4; c++)
                s[r][c] += qv[r].x * kv[c].x + qv[r].y * kv[c].y
                         + qv[r].z * kv[c].z + qv[r].w * kv[c].w;
    }

    float den[4];
    #pragma unroll
    for (int r = 0; r < 4; r++) {
        float mx = fmaxf(fmaxf(s[r][0], s[r][1]), fmaxf(s[r][2], s[r][3]));
        mx = fmaxf(mx, __shfl_xor_sync(0xFFFFFFFFu, mx, 1));
        mx = fmaxf(mx, __shfl_xor_sync(0xFFFFFFFFu, mx, 2));
        float sum = 0.0f;
        #pragma unroll
        for (int c = 0; c < 4; c++) {
            s[r][c] = __expf((s[r][c] - mx) * 0.125f);
            sum += s[r][c];
        }
        sum += __shfl_xor_sync(0xFFFFFFFFu, sum, 1);
        sum += __shfl_xor_sync(0xFFFFFFFFu, sum, 2);
        den[r] = 1.0f / sum;
    }

    float* P = tb + POFF;
    #pragma unroll
    for (int r = 0; r < 4; r++)
        #pragma unroll
        for (int c = 0; c < 4; c++)
            P[(4 * I + r) * 17 + (4 * J + c)] = s[r][c];
    __syncwarp();

    float o[4][16];
    #pragma unroll
    for (int r = 0; r < 4; r++)
        #pragma unroll
        for (int cc = 0; cc < 16; cc++) o[r][cc] = 0.0f;

    #pragma unroll
    for (int g = 0; g < 16; g++) {
        float a[4];
        #pragma unroll
        for (int r = 0; r < 4; r++) a[r] = P[(4 * I + r) * 17 + g];
        const float* vr = tb + (3 * g + 2) * RPITCH + 16 * J;
        float4 v0 = *(const float4*)(vr);
        float4 v1 = *(const float4*)(vr + 4);
        float4 v2 = *(const float4*)(vr + 8);
        float4 v3 = *(const float4*)(vr + 12);
        #pragma unroll
        for (int r = 0; r < 4; r++) {
            o[r][0]  += a[r] * v0.x;  o[r][1]  += a[r] * v0.y;
            o[r][2]  += a[r] * v0.z;  o[r][3]  += a[r] * v0.w;
            o[r][4]  += a[r] * v1.x;  o[r][5]  += a[r] * v1.y;
            o[r][6]  += a[r] * v1.z;  o[r][7]  += a[r] * v1.w;
            o[r][8]  += a[r] * v2.x;  o[r][9]  += a[r] * v2.y;
            o[r][10] += a[r] * v2.z;  o[r][11] += a[r] * v2.w;
            o[r][12] += a[r] * v3.x;  o[r][13] += a[r] * v3.y;
            o[r][14] += a[r] * v3.z;  o[r][15] += a[r] * v3.w;
        }
    }

    float* yt = y + (size_t)(tokBlk + tok) * CDIM;
    #pragma unroll
    for (int r = 0; r < 4; r++) {
        const int h = 4 * I + r;
        #pragma unroll
        for (int q = 0; q < 4; q++) {
            uint4 w;
            w.x = f2tf32(o[r][q * 4 + 0] * den[r]);
            w.y = f2tf32(o[r][q * 4 + 1] * den[r]);
            w.z = f2tf32(o[r][q * 4 + 2] * den[r]);
            w.w = f2tf32(o[r][q * 4 + 3] * den[r]);
            *(uint4*)(yt + h * 64 + 16 * J + q * 4) = w;
        }
    }
}

// ---------------------------------------------------------------------------
extern "C" void kernel_launch(void* const* d_in, const int* in_sizes, int n_in,
                              void* d_out, int out_size)
{
    const float* x    = (const float*)d_in[0];
    const float* Wqkv = (const float*)d_in[1];
    const float* Wout = (const float*)d_in[2];
    const float* bout = (const float*)d_in[3];
    float* out = (float*)d_out;

    float *qkv, *y, *xt, *w1t, *w2t;
    cudaGetSymbolAddress((void**)&qkv, g_qkv);
    cudaGetSymbolAddress((void**)&y,   g_y);
    cudaGetSymbolAddress((void**)&xt,  g_xt);
    cudaGetSymbolAddress((void**)&w1t, g_w1t);
    cudaGetSymbolAddress((void**)&w2t, g_w2t);

    cudaFuncSetAttribute(tf32_gemm,    cudaFuncAttributeMaxDynamicSharedMemorySize, SMEM_B);
    cudaFuncSetAttribute(tf32_gemm_64, cudaFuncAttributeMaxDynamicSharedMemorySize, SMEM64);
    cudaFuncSetAttribute(attn_kernel,  cudaFuncAttributeMaxDynamicSharedMemorySize, ATTN_SMEM);

    // merged tf32 rounding pass (x, Wqkv, Wout)
    round_all_kernel<<<2960, 256>>>(x, xt, Wqkv, w1t, Wout, w2t);

    // GEMM1: qkv = xt @ w1t^T   (16384 x 3072, K=1024) — 128x128 tiles
    tf32_gemm<<<dim3(C3 / 128, NTOK / 128), 256, SMEM_B>>>(
        xt, w1t, nullptr, qkv, NTOK, C3, CDIM);

    // attention over heads (emits tf32-rounded y)
    attn_kernel<<<NTOK / TOKPC, 128, ATTN_SMEM>>>(qkv, y);

    // GEMM2: out = y @ w2t^T + bout   (16384 x 1024, K=1024) — 64x128 tiles
    tf32_gemm_64<<<dim3(CDIM / 128, NTOK / 64), 256, SMEM64>>>(
        y, w2t, bout, out, NTOK, CDIM, CDIM);
}

// round 12
// speedup vs baseline: 1.5296x; 1.5296x over previous
#include <cuda_runtime.h>
#include <cuda_fp16.h>
#include <stdint.h>
#include <math.h>

// ---------------- problem constants ----------------
#define CDIM   1024
#define NTOK   16384             // B*T = 4*4096
#define C3     (3 * CDIM)        // 3072

// ---------------- scratch (allocation-free rule) ----------------
__device__ float  g_qkv[(size_t)NTOK * C3];     // fp32 qkv (precision-critical)
__device__ __half g_yh [(size_t)NTOK * CDIM];   // fp16 y
__device__ __half g_xh [(size_t)NTOK * CDIM];
__device__ __half g_w1h[(size_t)C3 * CDIM];
__device__ __half g_w2h[(size_t)CDIM * CDIM];

// ---------------- PTX helpers (baseline sm_80+ only) ----------------
__device__ __forceinline__ uint32_t smem_u32(const void* p) {
    uint32_t a;
    asm("{ .reg .u64 t; cvta.to.shared.u64 t, %1; cvt.u32.u64 %0, t; }"
        : "=r"(a) : "l"(p));
    return a;
}

#define CP_ASYNC16(dst_u32, src_ptr) \
    asm volatile("cp.async.cg.shared.global [%0], [%1], 16;" \
                 :: "r"(dst_u32), "l"(src_ptr) : "memory")
#define CP_COMMIT() asm volatile("cp.async.commit_group;" ::: "memory")
#define CP_WAIT(n)  asm volatile("cp.async.wait_group %0;" :: "n"(n) : "memory")

#define LDSM4(r, addr) \
    asm volatile("ldmatrix.sync.aligned.m8n8.x4.shared.b16 {%0,%1,%2,%3}, [%4];" \
        : "=r"((r)[0]), "=r"((r)[1]), "=r"((r)[2]), "=r"((r)[3]) : "r"(addr))

// single-pass fp16 m16n8k16, fp32 accumulate
#define MMA_F16(d, a, b0, b1) \
    asm volatile("mma.sync.aligned.m16n8k16.row.col.f32.f16.f16.f32 " \
        "{%0,%1,%2,%3}, {%4,%5,%6,%7}, {%8,%9}, {%0,%1,%2,%3};" \
        : "+f"((d)[0]), "+f"((d)[1]), "+f"((d)[2]), "+f"((d)[3]) \
        : "r"((a)[0]), "r"((a)[1]), "r"((a)[2]), "r"((a)[3]), "r"(b0), "r"(b1))

// ---------------- smem geometry (pitch 80 B — R3-proven conflict-free) ----------------
// 8 rows @ 20-word stride hit all 32 banks exactly once for ldmatrix.
#define PITCH80  80
#define TILEH_B  (128 * PITCH80)        // 10240 B (128 rows x 32 halves)
#define OFFH_B   TILEH_B
#define STGH_B   (2 * TILEH_B)          // 20480 B
#define NSTGH    3
#define SMEMH    (NSTGH * STGH_B)       // 61440 B -> 2 CTAs/SM (smem+regs)
#define BKCH     32                     // K halves per chunk (2 k16 steps)

// ---------------------------------------------------------------------------
// C[M,N] = A[M,K] @ B[N,K]^T (+bias); A,B fp16, fp32 accum/output.
// 128x128 CTA tile, 8 warps (64x32 each), 3-stage cp.async, 2 CTAs/SM.
// ---------------------------------------------------------------------------
__global__ __launch_bounds__(256, 2) void f16_gemm(
    const __half* __restrict__ A, const __half* __restrict__ B,
    const float* __restrict__ bias, float* __restrict__ C,
    int M, int N, int K)
{
    extern __shared__ char sm[];
    const uint32_t sbase = smem_u32(sm);

    const int tid  = threadIdx.x;
    const int lane = tid & 31;
    const int wid  = tid >> 5;
    const int wm   = wid & 1;       // M half
    const int wn   = wid >> 1;      // N quarter
    const int bm   = blockIdx.y * 128;
    const int bn   = blockIdx.x * 128;

    // ---- loader: 128 rows x 4 chunks(16B); 2 chunks per thread ----
    const int lr = tid >> 1;              // 0..127
    const int lc = (tid & 1) * 2;         // chunk 0 or 2
    const __half* gA = A + (size_t)(bm + lr) * K + lc * 8;
    const __half* gB = B + (size_t)(bn + lr) * K + lc * 8;
    const uint32_t sRow = (uint32_t)(lr * PITCH80 + lc * 16);

    // ---- ldmatrix lane addressing (R3-proven) ----
    const uint32_t aOff = (uint32_t)((wm * 64 + (lane & 15)) * PITCH80 + (lane >> 4) * 16);
    const uint32_t bOff = (uint32_t)((wn * 32 + (lane & 15)) * PITCH80 + (lane >> 4) * 16);

    float acc[4][4][4];
    #pragma unroll
    for (int i = 0; i < 4; i++)
        #pragma unroll
        for (int j = 0; j < 4; j++)
            #pragma unroll
            for (int q = 0; q < 4; q++) acc[i][j][q] = 0.0f;

    const int KC = K / BKCH;

    auto issue = [&](int stg, int ko) {
        const uint32_t dA = sbase + (uint32_t)stg * STGH_B + sRow;
        const uint32_t dB = dA + OFFH_B;
        const __half* sa = gA + ko;
        const __half* sb = gB + ko;
        CP_ASYNC16(dA,      sa);
        CP_ASYNC16(dA + 16, sa + 8);
        CP_ASYNC16(dB,      sb);
        CP_ASYNC16(dB + 16, sb + 8);
    };

    // prologue: 2 stages in flight
    issue(0, 0);    CP_COMMIT();
    issue(1, BKCH); CP_COMMIT();

    uint32_t ah[2][4][4], bh[2][2][4];

    for (int c = 0; c < KC; c++) {
        if (c == KC - 1) { CP_WAIT(0); } else { CP_WAIT(1); }
        __syncthreads();
        if (c + 2 < KC) { issue((c + 2) % NSTGH, (c + 2) * BKCH); CP_COMMIT(); }

        const uint32_t stg = sbase + (uint32_t)(c % NSTGH) * STGH_B;
        const uint32_t aB  = stg + aOff;
        const uint32_t bB  = stg + OFFH_B + bOff;

        // frags for k16-step 0
        #pragma unroll
        for (int i = 0; i < 4; i++) LDSM4(ah[0][i], aB + (uint32_t)(i * 16 * PITCH80));
        #pragma unroll
        for (int p = 0; p < 2; p++) LDSM4(bh[0][p], bB + (uint32_t)(p * 16 * PITCH80));

        #pragma unroll
        for (int s = 0; s < 2; s++) {
            const int cur = s & 1;
            const int nxt = cur ^ 1;
            #pragma unroll
            for (int m = 0; m < 16; m++) {
                const int i = m >> 2, j = m & 3;
                const int nb = j >> 1, jj = j & 1;
                const uint32_t b0 = jj ? bh[cur][nb][1] : bh[cur][nb][0];
                const uint32_t b1 = jj ? bh[cur][nb][3] : bh[cur][nb][2];
                MMA_F16(acc[i][j], ah[cur][i], b0, b1);
                if (s == 0) {   // interleave next-step frag loads
                    if (m == 2)
                        LDSM4(ah[nxt][0], aB + 32 + (uint32_t)(0 * 16 * PITCH80));
                    if (m == 4)
                        LDSM4(ah[nxt][1], aB + 32 + (uint32_t)(1 * 16 * PITCH80));
                    if (m == 6)
                        LDSM4(ah[nxt][2], aB + 32 + (uint32_t)(2 * 16 * PITCH80));
                    if (m == 8)
                        LDSM4(ah[nxt][3], aB + 32 + (uint32_t)(3 * 16 * PITCH80));
                    if (m == 10)
                        LDSM4(bh[nxt][0], bB + 32 + (uint32_t)(0 * 16 * PITCH80));
                    if (m == 12)
                        LDSM4(bh[nxt][1], bB + 32 + (uint32_t)(1 * 16 * PITCH80));
                }
            }
        }
    }

    // ---- epilogue ----
    #pragma unroll
    for (int i = 0; i < 4; i++) {
        const int row = bm + wm * 64 + i * 16 + (lane >> 2);
        #pragma unroll
        for (int j = 0; j < 4; j++) {
            const int col = bn + wn * 32 + j * 8 + (lane & 3) * 2;
            float b0 = 0.f, b1 = 0.f;
            if (bias) { b0 = bias[col]; b1 = bias[col + 1]; }
            float2 v0 = make_float2(acc[i][j][0] + b0, acc[i][j][1] + b1);
            float2 v1 = make_float2(acc[i][j][2] + b0, acc[i][j][3] + b1);
            *(float2*)(C + (size_t)row * N + col)       = v0;
            *(float2*)(C + (size_t)(row + 8) * N + col) = v1;
        }
    }
}

// ---------------------------------------------------------------------------
// Merged fp32 -> fp16 conversion: x, Wqkv, Wout in one grid-stride launch.
// ---------------------------------------------------------------------------
#define N4_X  (NTOK * CDIM / 4)
#define N4_W1 (C3 * CDIM / 4)
#define N4_W2 (CDIM * CDIM / 4)

__global__ __launch_bounds__(256) void cvt_all_kernel(
    const float* __restrict__ x,  __half* __restrict__ xh,
    const float* __restrict__ w1, __half* __restrict__ w1h,
    const float* __restrict__ w2, __half* __restrict__ w2h)
{
    const int total = N4_X + N4_W1 + N4_W2;
    for (int i = blockIdx.x * blockDim.x + threadIdx.x; i < total;
         i += gridDim.x * blockDim.x) {
        const float4* s;
        __half* d;
        int k;
        if (i < N4_X)              { s = (const float4*)x;  d = xh;  k = i; }
        else if (i < N4_X + N4_W1) { s = (const float4*)w1; d = w1h; k = i - N4_X; }
        else                       { s = (const float4*)w2; d = w2h; k = i - N4_X - N4_W1; }
        const float4 v = s[k];
        __half2 h0 = __floats2half2_rn(v.x, v.y);
        __half2 h1 = __floats2half2_rn(v.z, v.w);
        uint2 r;
        r.x = *(uint32_t*)&h0;
        r.y = *(uint32_t*)&h1;
        *(uint2*)(d + (size_t)k * 4) = r;
    }
}

// ---------------------------------------------------------------------------
// Attention over heads — register-tiled (round 10), fp16 output.
// ---------------------------------------------------------------------------
#define TOKPC  8
#define RPITCH 68
#define POFF   3264
#define TPITCH 3544
#define ATTN_SMEM (TOKPC * TPITCH * 4)

__global__ __launch_bounds__(128) void attn_kernel(
    const float* __restrict__ qkv, __half* __restrict__ y)
{
    extern __shared__ float sh[];
    const int tid = threadIdx.x;
    const int tokBlk = blockIdx.x * TOKPC;

    const float4* src = (const float4*)(qkv + (size_t)tokBlk * C3);
    #pragma unroll
    for (int it = 0; it < (TOKPC * 768) / 128; it++) {
        const int i  = it * 128 + tid;
        const int t  = i / 768;
        const int rr = (i % 768) >> 4;
        const int c4 = i & 15;
        *(float4*)(sh + t * TPITCH + rr * RPITCH + c4 * 4) = src[i];
    }
    __syncthreads();

    const int tok = tid >> 4;
    const int j   = tid & 15;
    const int I   = j >> 2;
    const int J   = j & 3;
    float* tb = sh + tok * TPITCH;

    float s[4][4];
    #pragma unroll
    for (int r = 0; r < 4; r++)
        #pragma unroll
        for (int c = 0; c < 4; c++) s[r][c] = 0.0f;

    #pragma unroll
    for (int dd = 0; dd < 16; dd++) {
        float4 qv[4], kv[4];
        #pragma unroll
        for (int r = 0; r < 4; r++)
            qv[r] = *(const float4*)(tb + (12 * I + 3 * r) * RPITCH + dd * 4);
        #pragma unroll
        for (int c = 0; c < 4; c++)
            kv[c] = *(const float4*)(tb + (12 * J + 3 * c + 1) * RPITCH + dd * 4);
        #pragma unroll
        for (int r = 0; r < 4; r++)
            #pragma unroll
            for (int c = 0; c < 4; c++)
                s[r][c] += qv[r].x * kv[c].x + qv[r].y * kv[c].y
                         + qv[r].z * kv[c].z + qv[r].w * kv[c].w;
    }

    float den[4];
    #pragma unroll
    for (int r = 0; r < 4; r++) {
        float mx = fmaxf(fmaxf(s[r][0], s[r][1]), fmaxf(s[r][2], s[r][3]));
        mx = fmaxf(mx, __shfl_xor_sync(0xFFFFFFFFu, mx, 1));
        mx = fmaxf(mx, __shfl_xor_sync(0xFFFFFFFFu, mx, 2));
        float sum = 0.0f;
        #pragma unroll
        for (int c = 0; c < 4; c++) {
            s[r][c] = __expf((s[r][c] - mx) * 0.125f);
            sum += s[r][c];
        }
        sum += __shfl_xor_sync(0xFFFFFFFFu, sum, 1);
        sum += __shfl_xor_sync(0xFFFFFFFFu, sum, 2);
        den[r] = 1.0f / sum;
    }

    float* P = tb + POFF;
    #pragma unroll
    for (int r = 0; r < 4; r++)
        #pragma unroll
        for (int c = 0; c < 4; c++)
            P[(4 * I + r) * 17 + (4 * J + c)] = s[r][c];
    __syncwarp();

    float o[4][16];
    #pragma unroll
    for (int r = 0; r < 4; r++)
        #pragma unroll
        for (int cc = 0; cc < 16; cc++) o[r][cc] = 0.0f;

    #pragma unroll
    for (int g = 0; g < 16; g++) {
        float a[4];
        #pragma unroll
        for (int r = 0; r < 4; r++) a[r] = P[(4 * I + r) * 17 + g];
        const float* vr = tb + (3 * g + 2) * RPITCH + 16 * J;
        float4 v0 = *(const float4*)(vr);
        float4 v1 = *(const float4*)(vr + 4);
        float4 v2 = *(const float4*)(vr + 8);
        float4 v3 = *(const float4*)(vr + 12);
        #pragma unroll
        for (int r = 0; r < 4; r++) {
            o[r][0]  += a[r] * v0.x;  o[r][1]  += a[r] * v0.y;
            o[r][2]  += a[r] * v0.z;  o[r][3]  += a[r] * v0.w;
            o[r][4]  += a[r] * v1.x;  o[r][5]  += a[r] * v1.y;
            o[r][6]  += a[r] * v1.z;  o[r][7]  += a[r] * v1.w;
            o[r][8]  += a[r] * v2.x;  o[r][9]  += a[r] * v2.y;
            o[r][10] += a[r] * v2.z;  o[r][11] += a[r] * v2.w;
            o[r][12] += a[r] * v3.x;  o[r][13] += a[r] * v3.y;
            o[r][14] += a[r] * v3.z;  o[r][15] += a[r] * v3.w;
        }
    }

    // ---- store y as fp16 (this rounding replaces the tf32 rounding) ----
    __half* yt = y + (size_t)(tokBlk + tok) * CDIM;
    #pragma unroll
    for (int r = 0; r < 4; r++) {
        const int h = 4 * I + r;
        #pragma unroll
        for (int qq = 0; qq < 2; qq++) {
            __half2 p0 = __floats2half2_rn(o[r][qq*8+0] * den[r], o[r][qq*8+1] * den[r]);
            __half2 p1 = __floats2half2_rn(o[r][qq*8+2] * den[r], o[r][qq*8+3] * den[r]);
            __half2 p2 = __floats2half2_rn(o[r][qq*8+4] * den[r], o[r][qq*8+5] * den[r]);
            __half2 p3 = __floats2half2_rn(o[r][qq*8+6] * den[r], o[r][qq*8+7] * den[r]);
            uint4 w;
            w.x = *(uint32_t*)&p0; w.y = *(uint32_t*)&p1;
            w.z = *(uint32_t*)&p2; w.w = *(uint32_t*)&p3;
            *(uint4*)(yt + h * 64 + 16 * J + qq * 8) = w;
        }
    }
}

// ---------------------------------------------------------------------------
extern "C" void kernel_launch(void* const* d_in, const int* in_sizes, int n_in,
                              void* d_out, int out_size)
{
    const float* x    = (const float*)d_in[0];
    const float* Wqkv = (const float*)d_in[1];
    const float* Wout = (const float*)d_in[2];
    const float* bout = (const float*)d_in[3];
    float* out = (float*)d_out;

    float* qkv;
    __half *yh, *xh, *w1h, *w2h;
    cudaGetSymbolAddress((void**)&qkv, g_qkv);
    cudaGetSymbolAddress((void**)&yh,  g_yh);
    cudaGetSymbolAddress((void**)&xh,  g_xh);
    cudaGetSymbolAddress((void**)&w1h, g_w1h);
    cudaGetSymbolAddress((void**)&w2h, g_w2h);

    cudaFuncSetAttribute(f16_gemm,   cudaFuncAttributeMaxDynamicSharedMemorySize, SMEMH);
    cudaFuncSetAttribute(attn_kernel, cudaFuncAttributeMaxDynamicSharedMemorySize, ATTN_SMEM);

    // merged fp16 conversion (x, Wqkv, Wout)
    cvt_all_kernel<<<2960, 256>>>(x, xh, Wqkv, w1h, Wout, w2h);

    // GEMM1: qkv = xh @ w1h^T   (16384 x 3072, K=1024), fp32 out
    f16_gemm<<<dim3(C3 / 128, NTOK / 128), 256, SMEMH>>>(
        xh, w1h, nullptr, qkv, NTOK, C3, CDIM);

    // attention over heads (fp32 in, fp16 out)
    attn_kernel<<<NTOK / TOKPC, 128, ATTN_SMEM>>>(qkv, yh);

    // GEMM2: out = yh @ w2h^T + bout   (16384 x 1024, K=1024)
    f16_gemm<<<dim3(CDIM / 128, NTOK / 128), 256, SMEMH>>>(
        yh, w2h, bout, out, NTOK, CDIM, CDIM);
}

// round 13
// speedup vs baseline: 1.6719x; 1.0930x over previous
#include <cuda_runtime.h>
#include <cuda_fp16.h>
#include <stdint.h>
#include <math.h>

// ---------------- problem constants ----------------
#define CDIM   1024
#define NTOK   16384             // B*T = 4*4096
#define C3     (3 * CDIM)        // 3072

// ---------------- scratch (allocation-free rule) ----------------
__device__ __half g_qkvh[(size_t)NTOK * C3];    // fp16 qkv
__device__ __half g_yh [(size_t)NTOK * CDIM];   // fp16 y
__device__ __half g_xh [(size_t)NTOK * CDIM];
__device__ __half g_w1h[(size_t)C3 * CDIM];
__device__ __half g_w2h[(size_t)CDIM * CDIM];

// ---------------- PTX helpers (baseline sm_80+ only) ----------------
__device__ __forceinline__ uint32_t smem_u32(const void* p) {
    uint32_t a;
    asm("{ .reg .u64 t; cvta.to.shared.u64 t, %1; cvt.u32.u64 %0, t; }"
        : "=r"(a) : "l"(p));
    return a;
}

#define CP_ASYNC16(dst_u32, src_ptr) \
    asm volatile("cp.async.cg.shared.global [%0], [%1], 16;" \
                 :: "r"(dst_u32), "l"(src_ptr) : "memory")
#define CP_COMMIT() asm volatile("cp.async.commit_group;" ::: "memory")
#define CP_WAIT(n)  asm volatile("cp.async.wait_group %0;" :: "n"(n) : "memory")

#define LDSM4(r, addr) \
    asm volatile("ldmatrix.sync.aligned.m8n8.x4.shared.b16 {%0,%1,%2,%3}, [%4];" \
        : "=r"((r)[0]), "=r"((r)[1]), "=r"((r)[2]), "=r"((r)[3]) : "r"(addr))

// single-pass fp16 m16n8k16, fp32 accumulate
#define MMA_F16(d, a, b0, b1) \
    asm volatile("mma.sync.aligned.m16n8k16.row.col.f32.f16.f16.f32 " \
        "{%0,%1,%2,%3}, {%4,%5,%6,%7}, {%8,%9}, {%0,%1,%2,%3};" \
        : "+f"((d)[0]), "+f"((d)[1]), "+f"((d)[2]), "+f"((d)[3]) \
        : "r"((a)[0]), "r"((a)[1]), "r"((a)[2]), "r"((a)[3]), "r"(b0), "r"(b1))

// ---------------- smem geometry (XOR swizzle, 128 B rows — R5-proven) ----------------
// Row = 64 halves = 8 chunks of 16 B; chunk' = chunk ^ (row & 7).
#define PITCH   128
#define TILE_B  (128 * PITCH)      // 16384 B
#define OFF_B   TILE_B
#define STAGE_B (2 * TILE_B)       // 32768 B
#define NSTG    3
#define SMEM_B  (NSTG * STAGE_B)   // 98304 B -> 2 CTAs/SM
#define BKC     64                 // K halves per chunk (4 k16 steps)

// ---------------------------------------------------------------------------
// C = A[M,K] @ B[N,K]^T (+bias); A,B fp16, fp32 accum.
// Output: fp32 to C if Ch==nullptr, else fp16 to Ch.
// 128x128 CTA tile, 8 warps (64x32), 3-stage cp.async, 2 CTAs/SM,
// XOR-swizzled smem, LDSM interleaved into MMA stream.
// ---------------------------------------------------------------------------
__global__ __launch_bounds__(256, 2) void f16_gemm(
    const __half* __restrict__ A, const __half* __restrict__ B,
    const float* __restrict__ bias, float* __restrict__ C,
    __half* __restrict__ Ch, int M, int N, int K)
{
    extern __shared__ char sm[];
    const uint32_t sbase = smem_u32(sm);

    const int tid  = threadIdx.x;
    const int lane = tid & 31;
    const int wid  = tid >> 5;
    const int wm   = wid & 1;       // M half
    const int wn   = wid >> 1;      // N quarter
    const int bm   = blockIdx.y * 128;
    const int bn   = blockIdx.x * 128;

    // ---- loader: 128 rows x 8 chunks; thread -> (row tid>>1, chunk-quad tid&1) ----
    const int lr = tid >> 1;
    const int lh = tid & 1;
    const __half* gA = A + (size_t)(bm + lr) * K + lh * 32;
    const __half* gB = B + (size_t)(bn + lr) * K + lh * 32;
    uint32_t sw[4];
    #pragma unroll
    for (int j = 0; j < 4; j++) sw[j] = (uint32_t)(((lh * 4 + j) ^ (lr & 7)) << 4);
    const uint32_t sRowBase = (uint32_t)(lr * PITCH);

    // ---- ldmatrix lane addressing ----
    // rows: base + (lane&15); base multiple of 16 -> row&7 == lane&7
    const int l8 = lane & 7;
    const int cg = lane >> 4;            // 16B chunk group (0/1) within k16
    const uint32_t aRow = (uint32_t)((wm * 64 + (lane & 15)) * PITCH);
    const uint32_t bRow = (uint32_t)((wn * 32 + (lane & 15)) * PITCH);
    uint32_t kSw[4];                     // swizzled chunk offset per k16-step
    #pragma unroll
    for (int s = 0; s < 4; s++)
        kSw[s] = (uint32_t)(((s * 2 + cg) ^ l8) << 4);

    float acc[4][4][4];
    #pragma unroll
    for (int i = 0; i < 4; i++)
        #pragma unroll
        for (int j = 0; j < 4; j++)
            #pragma unroll
            for (int q = 0; q < 4; q++) acc[i][j][q] = 0.0f;

    const int KC = K / BKC;   // 16

    auto issue = [&](int stg, int ko) {
        const uint32_t dA = sbase + (uint32_t)stg * STAGE_B + sRowBase;
        const uint32_t dB = dA + OFF_B;
        const __half* sa = gA + ko;
        const __half* sb = gB + ko;
        #pragma unroll
        for (int j = 0; j < 4; j++) {
            CP_ASYNC16(dA + sw[j], sa + j * 8);
            CP_ASYNC16(dB + sw[j], sb + j * 8);
        }
    };

    issue(0, 0);   CP_COMMIT();
    issue(1, BKC); CP_COMMIT();

    uint32_t ah[2][4][4], bh[2][2][4];

    for (int c = 0; c < KC; c++) {
        if (c == KC - 1) { CP_WAIT(0); } else { CP_WAIT(1); }
        __syncthreads();
        if (c + 2 < KC) { issue((c + 2) % NSTG, (c + 2) * BKC); CP_COMMIT(); }

        const uint32_t stg = sbase + (uint32_t)(c % NSTG) * STAGE_B;
        const uint32_t aB  = stg + aRow;
        const uint32_t bB  = stg + OFF_B + bRow;

        // frags for k16-step 0
        #pragma unroll
        for (int i = 0; i < 4; i++) LDSM4(ah[0][i], aB + kSw[0] + (uint32_t)(i * 16 * PITCH));
        #pragma unroll
        for (int p = 0; p < 2; p++) LDSM4(bh[0][p], bB + kSw[0] + (uint32_t)(p * 16 * PITCH));

        #pragma unroll
        for (int s = 0; s < 4; s++) {
            const int cur = s & 1;
            const int nxt = cur ^ 1;
            #pragma unroll
            for (int m = 0; m < 16; m++) {
                const int i = m >> 2, j = m & 3;
                const int nb = j >> 1, jj = j & 1;
                const uint32_t b0 = jj ? bh[cur][nb][1] : bh[cur][nb][0];
                const uint32_t b1 = jj ? bh[cur][nb][3] : bh[cur][nb][2];
                MMA_F16(acc[i][j], ah[cur][i], b0, b1);
                if (s < 3) {   // weave next-step frag loads into MMA stream
                    if (m == 2)
                        LDSM4(ah[nxt][0], aB + kSw[s + 1] + (uint32_t)(0 * 16 * PITCH));
                    if (m == 4)
                        LDSM4(ah[nxt][1], aB + kSw[s + 1] + (uint32_t)(1 * 16 * PITCH));
                    if (m == 6)
                        LDSM4(ah[nxt][2], aB + kSw[s + 1] + (uint32_t)(2 * 16 * PITCH));
                    if (m == 8)
                        LDSM4(ah[nxt][3], aB + kSw[s + 1] + (uint32_t)(3 * 16 * PITCH));
                    if (m == 10)
                        LDSM4(bh[nxt][0], bB + kSw[s + 1] + (uint32_t)(0 * 16 * PITCH));
                    if (m == 12)
                        LDSM4(bh[nxt][1], bB + kSw[s + 1] + (uint32_t)(1 * 16 * PITCH));
                }
            }
        }
    }

    // ---- epilogue: fp32 (C) or fp16 (Ch) output ----
    #pragma unroll
    for (int i = 0; i < 4; i++) {
        const int row = bm + wm * 64 + i * 16 + (lane >> 2);
        #pragma unroll
        for (int j = 0; j < 4; j++) {
            const int col = bn + wn * 32 + j * 8 + (lane & 3) * 2;
            float b0 = 0.f, b1 = 0.f;
            if (bias) { b0 = bias[col]; b1 = bias[col + 1]; }
            const float v00 = acc[i][j][0] + b0, v01 = acc[i][j][1] + b1;
            const float v10 = acc[i][j][2] + b0, v11 = acc[i][j][3] + b1;
            if (Ch) {
                __half2 h0 = __floats2half2_rn(v00, v01);
                __half2 h1 = __floats2half2_rn(v10, v11);
                *(__half2*)(Ch + (size_t)row * N + col)       = h0;
                *(__half2*)(Ch + (size_t)(row + 8) * N + col) = h1;
            } else {
                *(float2*)(C + (size_t)row * N + col)       = make_float2(v00, v01);
                *(float2*)(C + (size_t)(row + 8) * N + col) = make_float2(v10, v11);
            }
        }
    }
}

// ---------------------------------------------------------------------------
// Merged fp32 -> fp16 conversion: x, Wqkv, Wout in one grid-stride launch.
// ---------------------------------------------------------------------------
#define N4_X  (NTOK * CDIM / 4)
#define N4_W1 (C3 * CDIM / 4)
#define N4_W2 (CDIM * CDIM / 4)

__global__ __launch_bounds__(256) void cvt_all_kernel(
    const float* __restrict__ x,  __half* __restrict__ xh,
    const float* __restrict__ w1, __half* __restrict__ w1h,
    const float* __restrict__ w2, __half* __restrict__ w2h)
{
    const int total = N4_X + N4_W1 + N4_W2;
    for (int i = blockIdx.x * blockDim.x + threadIdx.x; i < total;
         i += gridDim.x * blockDim.x) {
        const float4* s;
        __half* d;
        int k;
        if (i < N4_X)              { s = (const float4*)x;  d = xh;  k = i; }
        else if (i < N4_X + N4_W1) { s = (const float4*)w1; d = w1h; k = i - N4_X; }
        else                       { s = (const float4*)w2; d = w2h; k = i - N4_X - N4_W1; }
        const float4 v = s[k];
        __half2 h0 = __floats2half2_rn(v.x, v.y);
        __half2 h1 = __floats2half2_rn(v.z, v.w);
        uint2 r;
        r.x = *(uint32_t*)&h0;
        r.y = *(uint32_t*)&h1;
        *(uint2*)(d + (size_t)k * 4) = r;
    }
}

// ---------------------------------------------------------------------------
// Attention over heads — register-tiled (R10 layout), fp16 qkv in, fp16 y out.
// qkv widened to fp32 in smem at load.
// ---------------------------------------------------------------------------
#define TOKPC  8
#define RPITCH 68
#define POFF   3264
#define TPITCH 3544
#define ATTN_SMEM (TOKPC * TPITCH * 4)

__global__ __launch_bounds__(128) void attn_kernel(
    const __half* __restrict__ qkv, __half* __restrict__ y)
{
    extern __shared__ float sh[];
    const int tid = threadIdx.x;
    const int tokBlk = blockIdx.x * TOKPC;

    // cooperative load: 8 tokens x 3072 halves; widen to fp32, pitch-68 rows
    const uint4* src = (const uint4*)(qkv + (size_t)tokBlk * C3);   // 8 halves per uint4
    #pragma unroll
    for (int it = 0; it < (TOKPC * 384) / 128; it++) {
        const int i  = it * 128 + tid;
        const int t  = i / 384;
        const int idx = i % 384;            // 8-half unit within token
        const int rr = idx >> 3;            // row (64 halves -> 8 units)
        const int c8 = idx & 7;
        const uint4 u = src[i];
        float* dst = sh + t * TPITCH + rr * RPITCH + c8 * 8;
        const __half2* hp = (const __half2*)&u;
        #pragma unroll
        for (int q = 0; q < 4; q++) {
            const float2 f = __half22float2(hp[q]);
            dst[q * 2 + 0] = f.x;
            dst[q * 2 + 1] = f.y;
        }
    }
    __syncthreads();

    const int tok = tid >> 4;
    const int j   = tid & 15;
    const int I   = j >> 2;
    const int J   = j & 3;
    float* tb = sh + tok * TPITCH;

    float s[4][4];
    #pragma unroll
    for (int r = 0; r < 4; r++)
        #pragma unroll
        for (int c = 0; c < 4; c++) s[r][c] = 0.0f;

    #pragma unroll
    for (int dd = 0; dd < 16; dd++) {
        float4 qv[4], kv[4];
        #pragma unroll
        for (int r = 0; r < 4; r++)
            qv[r] = *(const float4*)(tb + (12 * I + 3 * r) * RPITCH + dd * 4);
        #pragma unroll
        for (int c = 0; c < 4; c++)
            kv[c] = *(const float4*)(tb + (12 * J + 3 * c + 1) * RPITCH + dd * 4);
        #pragma unroll
        for (int r = 0; r < 4; r++)
            #pragma unroll
            for (int c = 0; c < 4; c++)
                s[r][c] += qv[r].x * kv[c].x + qv[r].y * kv[c].y
                         + qv[r].z * kv[c].z + qv[r].w * kv[c].w;
    }

    float den[4];
    #pragma unroll
    for (int r = 0; r < 4; r++) {
        float mx = fmaxf(fmaxf(s[r][0], s[r][1]), fmaxf(s[r][2], s[r][3]));
        mx = fmaxf(mx, __shfl_xor_sync(0xFFFFFFFFu, mx, 1));
        mx = fmaxf(mx, __shfl_xor_sync(0xFFFFFFFFu, mx, 2));
        float sum = 0.0f;
        #pragma unroll
        for (int c = 0; c < 4; c++) {
            s[r][c] = __expf((s[r][c] - mx) * 0.125f);
            sum += s[r][c];
        }
        sum += __shfl_xor_sync(0xFFFFFFFFu, sum, 1);
        sum += __shfl_xor_sync(0xFFFFFFFFu, sum, 2);
        den[r] = 1.0f / sum;
    }

    float* P = tb + POFF;
    #pragma unroll
    for (int r = 0; r < 4; r++)
        #pragma unroll
        for (int c = 0; c < 4; c++)
            P[(4 * I + r) * 17 + (4 * J + c)] = s[r][c];
    __syncwarp();

    float o[4][16];
    #pragma unroll
    for (int r = 0; r < 4; r++)
        #pragma unroll
        for (int cc = 0; cc < 16; cc++) o[r][cc] = 0.0f;

    #pragma unroll
    for (int g = 0; g < 16; g++) {
        float a[4];
        #pragma unroll
        for (int r = 0; r < 4; r++) a[r] = P[(4 * I + r) * 17 + g];
        const float* vr = tb + (3 * g + 2) * RPITCH + 16 * J;
        float4 v0 = *(const float4*)(vr);
        float4 v1 = *(const float4*)(vr + 4);
        float4 v2 = *(const float4*)(vr + 8);
        float4 v3 = *(const float4*)(vr + 12);
        #pragma unroll
        for (int r = 0; r < 4; r++) {
            o[r][0]  += a[r] * v0.x;  o[r][1]  += a[r] * v0.y;
            o[r][2]  += a[r] * v0.z;  o[r][3]  += a[r] * v0.w;
            o[r][4]  += a[r] * v1.x;  o[r][5]  += a[r] * v1.y;
            o[r][6]  += a[r] * v1.z;  o[r][7]  += a[r] * v1.w;
            o[r][8]  += a[r] * v2.x;  o[r][9]  += a[r] * v2.y;
            o[r][10] += a[r] * v2.z;  o[r][11] += a[r] * v2.w;
            o[r][12] += a[r] * v3.x;  o[r][13] += a[r] * v3.y;
            o[r][14] += a[r] * v3.z;  o[r][15] += a[r] * v3.w;
        }
    }

    __half* yt = y + (size_t)(tokBlk + tok) * CDIM;
    #pragma unroll
    for (int r = 0; r < 4; r++) {
        const int h = 4 * I + r;
        #pragma unroll
        for (int qq = 0; qq < 2; qq++) {
            __half2 p0 = __floats2half2_rn(o[r][qq*8+0] * den[r], o[r][qq*8+1] * den[r]);
            __half2 p1 = __floats2half2_rn(o[r][qq*8+2] * den[r], o[r][qq*8+3] * den[r]);
            __half2 p2 = __floats2half2_rn(o[r][qq*8+4] * den[r], o[r][qq*8+5] * den[r]);
            __half2 p3 = __floats2half2_rn(o[r][qq*8+6] * den[r], o[r][qq*8+7] * den[r]);
            uint4 w;
            w.x = *(uint32_t*)&p0; w.y = *(uint32_t*)&p1;
            w.z = *(uint32_t*)&p2; w.w = *(uint32_t*)&p3;
            *(uint4*)(yt + h * 64 + 16 * J + qq * 8) = w;
        }
    }
}

// ---------------------------------------------------------------------------
extern "C" void kernel_launch(void* const* d_in, const int* in_sizes, int n_in,
                              void* d_out, int out_size)
{
    const float* x    = (const float*)d_in[0];
    const float* Wqkv = (const float*)d_in[1];
    const float* Wout = (const float*)d_in[2];
    const float* bout = (const float*)d_in[3];
    float* out = (float*)d_out;

    __half *qkvh, *yh, *xh, *w1h, *w2h;
    cudaGetSymbolAddress((void**)&qkvh, g_qkvh);
    cudaGetSymbolAddress((void**)&yh,   g_yh);
    cudaGetSymbolAddress((void**)&xh,   g_xh);
    cudaGetSymbolAddress((void**)&w1h,  g_w1h);
    cudaGetSymbolAddress((void**)&w2h,  g_w2h);

    cudaFuncSetAttribute(f16_gemm,    cudaFuncAttributeMaxDynamicSharedMemorySize, SMEM_B);
    cudaFuncSetAttribute(attn_kernel, cudaFuncAttributeMaxDynamicSharedMemorySize, ATTN_SMEM);

    // merged fp16 conversion (x, Wqkv, Wout)
    cvt_all_kernel<<<2960, 256>>>(x, xh, Wqkv, w1h, Wout, w2h);

    // GEMM1: qkvh = xh @ w1h^T   (16384 x 3072, K=1024), fp16 out
    f16_gemm<<<dim3(C3 / 128, NTOK / 128), 256, SMEM_B>>>(
        xh, w1h, nullptr, nullptr, qkvh, NTOK, C3, CDIM);

    // attention over heads (fp16 in/out)
    attn_kernel<<<NTOK / TOKPC, 128, ATTN_SMEM>>>(qkvh, yh);

    // GEMM2: out = yh @ w2h^T + bout   (16384 x 1024, K=1024), fp32 out
    f16_gemm<<<dim3(CDIM / 128, NTOK / 128), 256, SMEM_B>>>(
        yh, w2h, bout, out, nullptr, NTOK, CDIM, CDIM);
}

// round 14
// speedup vs baseline: 1.7750x; 1.0617x over previous
#include <cuda_runtime.h>
#include <cuda_fp16.h>
#include <stdint.h>
#include <math.h>

// ---------------- problem constants ----------------
#define CDIM   1024
#define NTOK   16384             // B*T = 4*4096
#define C3     (3 * CDIM)        // 3072

// ---------------- scratch (allocation-free rule) ----------------
__device__ __half g_qkvh[(size_t)NTOK * C3];    // fp16 qkv
__device__ __half g_yh [(size_t)NTOK * CDIM];   // fp16 y
__device__ __half g_xh [(size_t)NTOK * CDIM];
__device__ __half g_w1h[(size_t)C3 * CDIM];
__device__ __half g_w2h[(size_t)CDIM * CDIM];

// ---------------- PTX helpers (baseline sm_80+ only) ----------------
__device__ __forceinline__ uint32_t smem_u32(const void* p) {
    uint32_t a;
    asm("{ .reg .u64 t; cvta.to.shared.u64 t, %1; cvt.u32.u64 %0, t; }"
        : "=r"(a) : "l"(p));
    return a;
}

#define CP_ASYNC16(dst_u32, src_ptr) \
    asm volatile("cp.async.cg.shared.global [%0], [%1], 16;" \
                 :: "r"(dst_u32), "l"(src_ptr) : "memory")
#define CP_COMMIT() asm volatile("cp.async.commit_group;" ::: "memory")
#define CP_WAIT(n)  asm volatile("cp.async.wait_group %0;" :: "n"(n) : "memory")

#define LDSM4(r, addr) \
    asm volatile("ldmatrix.sync.aligned.m8n8.x4.shared.b16 {%0,%1,%2,%3}, [%4];" \
        : "=r"((r)[0]), "=r"((r)[1]), "=r"((r)[2]), "=r"((r)[3]) : "r"(addr))

// single-pass fp16 m16n8k16, fp32 accumulate
#define MMA_F16(d, a, b0, b1) \
    asm volatile("mma.sync.aligned.m16n8k16.row.col.f32.f16.f16.f32 " \
        "{%0,%1,%2,%3}, {%4,%5,%6,%7}, {%8,%9}, {%0,%1,%2,%3};" \
        : "+f"((d)[0]), "+f"((d)[1]), "+f"((d)[2]), "+f"((d)[3]) \
        : "r"((a)[0]), "r"((a)[1]), "r"((a)[2]), "r"((a)[3]), "r"(b0), "r"(b1))

// ---------------- smem geometry (XOR swizzle, 128 B rows) ----------------
#define PITCH   128
#define TILE_B  (128 * PITCH)      // 16384 B
#define OFF_B   TILE_B
#define STAGE_B (2 * TILE_B)       // 32768 B
#define NSTG    3
#define SMEM_B  (NSTG * STAGE_B)   // 98304 B -> 2 CTAs/SM
#define BKC     64                 // K halves per chunk (4 k16 steps)
#define KFIX    1024               // compile-time K (both GEMMs)
#define KC      (KFIX / BKC)       // 16 chunks, fully unrolled

// ---------------------------------------------------------------------------
// C = A[M,K] @ B[N,K]^T (+bias); A,B fp16, fp32 accum. K = 1024 compile-time.
// OUT_HALF selects fp16 (Ch) vs fp32 (C) output at compile time.
// 128x128 CTA tile, 8 warps (64x32), 3-stage cp.async, 2 CTAs/SM,
// XOR-swizzled smem, LDSM interleaved into MMA stream, full KC unroll.
// ---------------------------------------------------------------------------
template <bool OUT_HALF>
__global__ __launch_bounds__(256, 2) void f16_gemm(
    const __half* __restrict__ A, const __half* __restrict__ B,
    const float* __restrict__ bias, float* __restrict__ C,
    __half* __restrict__ Ch, int M, int N)
{
    extern __shared__ char sm[];
    const uint32_t sbase = smem_u32(sm);

    const int tid  = threadIdx.x;
    const int lane = tid & 31;
    const int wid  = tid >> 5;
    const int wm   = wid & 1;       // M half
    const int wn   = wid >> 1;      // N quarter
    const int bm   = blockIdx.y * 128;
    const int bn   = blockIdx.x * 128;

    // ---- loader: 128 rows x 8 chunks; thread -> (row tid>>1, chunk-quad tid&1) ----
    const int lr = tid >> 1;
    const int lh = tid & 1;
    const __half* gA = A + (size_t)(bm + lr) * KFIX + lh * 32;
    const __half* gB = B + (size_t)(bn + lr) * KFIX + lh * 32;
    uint32_t sw[4];
    #pragma unroll
    for (int j = 0; j < 4; j++) sw[j] = (uint32_t)(((lh * 4 + j) ^ (lr & 7)) << 4);
    const uint32_t sRowBase = (uint32_t)(lr * PITCH);

    // ---- ldmatrix lane addressing ----
    const int l8 = lane & 7;
    const int cg = lane >> 4;            // 16B chunk group (0/1) within k16
    const uint32_t aRow = (uint32_t)((wm * 64 + (lane & 15)) * PITCH);
    const uint32_t bRow = (uint32_t)((wn * 32 + (lane & 15)) * PITCH);
    uint32_t kSw[4];                     // swizzled chunk offset per k16-step
    #pragma unroll
    for (int s = 0; s < 4; s++)
        kSw[s] = (uint32_t)(((s * 2 + cg) ^ l8) << 4);

    float acc[4][4][4];
    #pragma unroll
    for (int i = 0; i < 4; i++)
        #pragma unroll
        for (int j = 0; j < 4; j++)
            #pragma unroll
            for (int q = 0; q < 4; q++) acc[i][j][q] = 0.0f;

    auto issue = [&](int stg, int ko) {
        const uint32_t dA = sbase + (uint32_t)stg * STAGE_B + sRowBase;
        const uint32_t dB = dA + OFF_B;
        const __half* sa = gA + ko;
        const __half* sb = gB + ko;
        #pragma unroll
        for (int j = 0; j < 4; j++) {
            CP_ASYNC16(dA + sw[j], sa + j * 8);
            CP_ASYNC16(dB + sw[j], sb + j * 8);
        }
    };

    issue(0, 0);   CP_COMMIT();
    issue(1, BKC); CP_COMMIT();

    uint32_t ah[2][4][4], bh[2][2][4];

    #pragma unroll
    for (int c = 0; c < KC; c++) {      // fully unrolled: stage math is immediate
        if (c == KC - 1) { CP_WAIT(0); } else { CP_WAIT(1); }
        __syncthreads();
        if (c + 2 < KC) { issue((c + 2) % NSTG, (c + 2) * BKC); CP_COMMIT(); }

        const uint32_t stg = sbase + (uint32_t)((c % NSTG) * STAGE_B);
        const uint32_t aB  = stg + aRow;
        const uint32_t bB  = stg + OFF_B + bRow;

        // frags for k16-step 0
        #pragma unroll
        for (int i = 0; i < 4; i++) LDSM4(ah[0][i], aB + kSw[0] + (uint32_t)(i * 16 * PITCH));
        #pragma unroll
        for (int p = 0; p < 2; p++) LDSM4(bh[0][p], bB + kSw[0] + (uint32_t)(p * 16 * PITCH));

        #pragma unroll
        for (int s = 0; s < 4; s++) {
            const int cur = s & 1;
            const int nxt = cur ^ 1;
            #pragma unroll
            for (int m = 0; m < 16; m++) {
                const int i = m >> 2, j = m & 3;
                const int nb = j >> 1, jj = j & 1;
                const uint32_t b0 = jj ? bh[cur][nb][1] : bh[cur][nb][0];
                const uint32_t b1 = jj ? bh[cur][nb][3] : bh[cur][nb][2];
                MMA_F16(acc[i][j], ah[cur][i], b0, b1);
                if (s < 3) {   // weave next-step frag loads into MMA stream
                    if (m == 2)
                        LDSM4(ah[nxt][0], aB + kSw[s + 1] + (uint32_t)(0 * 16 * PITCH));
                    if (m == 4)
                        LDSM4(ah[nxt][1], aB + kSw[s + 1] + (uint32_t)(1 * 16 * PITCH));
                    if (m == 6)
                        LDSM4(ah[nxt][2], aB + kSw[s + 1] + (uint32_t)(2 * 16 * PITCH));
                    if (m == 8)
                        LDSM4(ah[nxt][3], aB + kSw[s + 1] + (uint32_t)(3 * 16 * PITCH));
                    if (m == 10)
                        LDSM4(bh[nxt][0], bB + kSw[s + 1] + (uint32_t)(0 * 16 * PITCH));
                    if (m == 12)
                        LDSM4(bh[nxt][1], bB + kSw[s + 1] + (uint32_t)(1 * 16 * PITCH));
                }
            }
        }
    }

    // ---- epilogue: compile-time fp32/fp16 output ----
    #pragma unroll
    for (int i = 0; i < 4; i++) {
        const int row = bm + wm * 64 + i * 16 + (lane >> 2);
        #pragma unroll
        for (int j = 0; j < 4; j++) {
            const int col = bn + wn * 32 + j * 8 + (lane & 3) * 2;
            float b0 = 0.f, b1 = 0.f;
            if (bias) { b0 = bias[col]; b1 = bias[col + 1]; }
            const float v00 = acc[i][j][0] + b0, v01 = acc[i][j][1] + b1;
            const float v10 = acc[i][j][2] + b0, v11 = acc[i][j][3] + b1;
            if (OUT_HALF) {
                __half2 h0 = __floats2half2_rn(v00, v01);
                __half2 h1 = __floats2half2_rn(v10, v11);
                *(__half2*)(Ch + (size_t)row * N + col)       = h0;
                *(__half2*)(Ch + (size_t)(row + 8) * N + col) = h1;
            } else {
                *(float2*)(C + (size_t)row * N + col)       = make_float2(v00, v01);
                *(float2*)(C + (size_t)(row + 8) * N + col) = make_float2(v10, v11);
            }
        }
    }
}

// ---------------------------------------------------------------------------
// Merged fp32 -> fp16 conversion: x, Wqkv, Wout in one grid-stride launch.
// ---------------------------------------------------------------------------
#define N4_X  (NTOK * CDIM / 4)
#define N4_W1 (C3 * CDIM / 4)
#define N4_W2 (CDIM * CDIM / 4)

__global__ __launch_bounds__(256) void cvt_all_kernel(
    const float* __restrict__ x,  __half* __restrict__ xh,
    const float* __restrict__ w1, __half* __restrict__ w1h,
    const float* __restrict__ w2, __half* __restrict__ w2h)
{
    const int total = N4_X + N4_W1 + N4_W2;
    for (int i = blockIdx.x * blockDim.x + threadIdx.x; i < total;
         i += gridDim.x * blockDim.x) {
        const float4* s;
        __half* d;
        int k;
        if (i < N4_X)              { s = (const float4*)x;  d = xh;  k = i; }
        else if (i < N4_X + N4_W1) { s = (const float4*)w1; d = w1h; k = i - N4_X; }
        else                       { s = (const float4*)w2; d = w2h; k = i - N4_X - N4_W1; }
        const float4 v = s[k];
        __half2 h0 = __floats2half2_rn(v.x, v.y);
        __half2 h1 = __floats2half2_rn(v.z, v.w);
        uint2 r;
        r.x = *(uint32_t*)&h0;
        r.y = *(uint32_t*)&h1;
        *(uint2*)(d + (size_t)k * 4) = r;
    }
}

// ---------------------------------------------------------------------------
// Attention over heads — register-tiled (R10 layout), fp16 in/out (R13).
// ---------------------------------------------------------------------------
#define TOKPC  8
#define RPITCH 68
#define POFF   3264
#define TPITCH 3544
#define ATTN_SMEM (TOKPC * TPITCH * 4)

__global__ __launch_bounds__(128) void attn_kernel(
    const __half* __restrict__ qkv, __half* __restrict__ y)
{
    extern __shared__ float sh[];
    const int tid = threadIdx.x;
    const int tokBlk = blockIdx.x * TOKPC;

    const uint4* src = (const uint4*)(qkv + (size_t)tokBlk * C3);
    #pragma unroll
    for (int it = 0; it < (TOKPC * 384) / 128; it++) {
        const int i  = it * 128 + tid;
        const int t  = i / 384;
        const int idx = i % 384;
        const int rr = idx >> 3;
        const int c8 = idx & 7;
        const uint4 u = src[i];
        float* dst = sh + t * TPITCH + rr * RPITCH + c8 * 8;
        const __half2* hp = (const __half2*)&u;
        #pragma unroll
        for (int q = 0; q < 4; q++) {
            const float2 f = __half22float2(hp[q]);
            dst[q * 2 + 0] = f.x;
            dst[q * 2 + 1] = f.y;
        }
    }
    __syncthreads();

    const int tok = tid >> 4;
    const int j   = tid & 15;
    const int I   = j >> 2;
    const int J   = j & 3;
    float* tb = sh + tok * TPITCH;

    float s[4][4];
    #pragma unroll
    for (int r = 0; r < 4; r++)
        #pragma unroll
        for (int c = 0; c < 4; c++) s[r][c] = 0.0f;

    #pragma unroll
    for (int dd = 0; dd < 16; dd++) {
        float4 qv[4], kv[4];
        #pragma unroll
        for (int r = 0; r < 4; r++)
            qv[r] = *(const float4*)(tb + (12 * I + 3 * r) * RPITCH + dd * 4);
        #pragma unroll
        for (int c = 0; c < 4; c++)
            kv[c] = *(const float4*)(tb + (12 * J + 3 * c + 1) * RPITCH + dd * 4);
        #pragma unroll
        for (int r = 0; r < 4; r++)
            #pragma unroll
            for (int c = 0; c < 4; c++)
                s[r][c] += qv[r].x * kv[c].x + qv[r].y * kv[c].y
                         + qv[r].z * kv[c].z + qv[r].w * kv[c].w;
    }

    float den[4];
    #pragma unroll
    for (int r = 0; r < 4; r++) {
        float mx = fmaxf(fmaxf(s[r][0], s[r][1]), fmaxf(s[r][2], s[r][3]));
        mx = fmaxf(mx, __shfl_xor_sync(0xFFFFFFFFu, mx, 1));
        mx = fmaxf(mx, __shfl_xor_sync(0xFFFFFFFFu, mx, 2));
        float sum = 0.0f;
        #pragma unroll
        for (int c = 0; c < 4; c++) {
            s[r][c] = __expf((s[r][c] - mx) * 0.125f);
            sum += s[r][c];
        }
        sum += __shfl_xor_sync(0xFFFFFFFFu, sum, 1);
        sum += __shfl_xor_sync(0xFFFFFFFFu, sum, 2);
        den[r] = 1.0f / sum;
    }

    float* P = tb + POFF;
    #pragma unroll
    for (int r = 0; r < 4; r++)
        #pragma unroll
        for (int c = 0; c < 4; c++)
            P[(4 * I + r) * 17 + (4 * J + c)] = s[r][c];
    __syncwarp();

    float o[4][16];
    #pragma unroll
    for (int r = 0; r < 4; r++)
        #pragma unroll
        for (int cc = 0; cc < 16; cc++) o[r][cc] = 0.0f;

    #pragma unroll
    for (int g = 0; g < 16; g++) {
        float a[4];
        #pragma unroll
        for (int r = 0; r < 4; r++) a[r] = P[(4 * I + r) * 17 + g];
        const float* vr = tb + (3 * g + 2) * RPITCH + 16 * J;
        float4 v0 = *(const float4*)(vr);
        float4 v1 = *(const float4*)(vr + 4);
        float4 v2 = *(const float4*)(vr + 8);
        float4 v3 = *(const float4*)(vr + 12);
        #pragma unroll
        for (int r = 0; r < 4; r++) {
            o[r][0]  += a[r] * v0.x;  o[r][1]  += a[r] * v0.y;
            o[r][2]  += a[r] * v0.z;  o[r][3]  += a[r] * v0.w;
            o[r][4]  += a[r] * v1.x;  o[r][5]  += a[r] * v1.y;
            o[r][6]  += a[r] * v1.z;  o[r][7]  += a[r] * v1.w;
            o[r][8]  += a[r] * v2.x;  o[r][9]  += a[r] * v2.y;
            o[r][10] += a[r] * v2.z;  o[r][11] += a[r] * v2.w;
            o[r][12] += a[r] * v3.x;  o[r][13] += a[r] * v3.y;
            o[r][14] += a[r] * v3.z;  o[r][15] += a[r] * v3.w;
        }
    }

    __half* yt = y + (size_t)(tokBlk + tok) * CDIM;
    #pragma unroll
    for (int r = 0; r < 4; r++) {
        const int h = 4 * I + r;
        #pragma unroll
        for (int qq = 0; qq < 2; qq++) {
            __half2 p0 = __floats2half2_rn(o[r][qq*8+0] * den[r], o[r][qq*8+1] * den[r]);
            __half2 p1 = __floats2half2_rn(o[r][qq*8+2] * den[r], o[r][qq*8+3] * den[r]);
            __half2 p2 = __floats2half2_rn(o[r][qq*8+4] * den[r], o[r][qq*8+5] * den[r]);
            __half2 p3 = __floats2half2_rn(o[r][qq*8+6] * den[r], o[r][qq*8+7] * den[r]);
            uint4 w;
            w.x = *(uint32_t*)&p0; w.y = *(uint32_t*)&p1;
            w.z = *(uint32_t*)&p2; w.w = *(uint32_t*)&p3;
            *(uint4*)(yt + h * 64 + 16 * J + qq * 8) = w;
        }
    }
}

// ---------------------------------------------------------------------------
extern "C" void kernel_launch(void* const* d_in, const int* in_sizes, int n_in,
                              void* d_out, int out_size)
{
    const float* x    = (const float*)d_in[0];
    const float* Wqkv = (const float*)d_in[1];
    const float* Wout = (const float*)d_in[2];
    const float* bout = (const float*)d_in[3];
    float* out = (float*)d_out;

    __half *qkvh, *yh, *xh, *w1h, *w2h;
    cudaGetSymbolAddress((void**)&qkvh, g_qkvh);
    cudaGetSymbolAddress((void**)&yh,   g_yh);
    cudaGetSymbolAddress((void**)&xh,   g_xh);
    cudaGetSymbolAddress((void**)&w1h,  g_w1h);
    cudaGetSymbolAddress((void**)&w2h,  g_w2h);

    cudaFuncSetAttribute(f16_gemm<true>,  cudaFuncAttributeMaxDynamicSharedMemorySize, SMEM_B);
    cudaFuncSetAttribute(f16_gemm<false>, cudaFuncAttributeMaxDynamicSharedMemorySize, SMEM_B);
    cudaFuncSetAttribute(attn_kernel,     cudaFuncAttributeMaxDynamicSharedMemorySize, ATTN_SMEM);

    // merged fp16 conversion (x, Wqkv, Wout)
    cvt_all_kernel<<<2960, 256>>>(x, xh, Wqkv, w1h, Wout, w2h);

    // GEMM1: qkvh = xh @ w1h^T   (16384 x 3072, K=1024), fp16 out
    f16_gemm<true><<<dim3(C3 / 128, NTOK / 128), 256, SMEM_B>>>(
        xh, w1h, nullptr, nullptr, qkvh, NTOK, C3);

    // attention over heads (fp16 in/out)
    attn_kernel<<<NTOK / TOKPC, 128, ATTN_SMEM>>>(qkvh, yh);

    // GEMM2: out = yh @ w2h^T + bout   (16384 x 1024, K=1024), fp32 out
    f16_gemm<false><<<dim3(CDIM / 128, NTOK / 128), 256, SMEM_B>>>(
        yh, w2h, bout, out, nullptr, NTOK, CDIM);
}